// round 12
// baseline (speedup 1.0000x reference)
#include <cuda_runtime.h>
#include <cstdint>

#define MM 1024
#define NN 4096
#define TCAND 4
#define FULLMASK 0xffffffffu

typedef unsigned int       u32;
typedef unsigned long long u64;

// ---------------- device scratch (no allocations allowed) ----------------
__device__ int   g_colhit[NN];
__device__ u32   g_colbits[NN / 32];
__device__ float g_rowmax[MM];
__device__ float g_rowsum[MM];
__device__ u64   g_cand[MM * TCAND];   // per-row top-4: key<<32 | col
__device__ float g_gmax;
__device__ float g_gsum;

__device__ __forceinline__ u32 orderKey(float v) {
    u32 b = __float_as_uint(v);
    return (b & 0x80000000u) ? ~b : (b | 0x80000000u);
}
// Packed head: key high, inverted flat index (row<<12|col) low 23 bits.
// u64 max == (max value, then smallest flat index) — exact reference tie-break.
__device__ __forceinline__ u64 packHead(u32 key, u32 rc) {
    return ((u64)key << 23) | (u64)(0x400000u - rc);
}
__device__ __forceinline__ u64 u64max(u64 a, u64 b) { return a > b ? a : b; }

#define INS3(h) do { u64 _h = (h); \
    if (_h > x2) { if (_h > x1) { x3 = x2; x2 = x1; x1 = _h; } \
                   else         { x3 = x2; x2 = _h; } } \
    else if (_h > x3) x3 = _h; } while (0)

// Pop row rr's candidate list to the first free column; writes sheads[rr]
// on success, else flags rs=rr for a cooperative rescan.
#define POPROW(rr, rs) do { \
    int _p = hptr[rr]; u64 _np = 0ull; \
    if (_p >= TCAND) { rs = (rr); } else { \
        while (_p < TCAND) { \
            u64 _cd = scand[((rr) << 2) + _p]; _p++; \
            u32 _kk = (u32)(_cd >> 32); \
            if (!_kk) { _p = TCAND; break; } \
            u32 _cc = (u32)_cd & 0xFFFu; \
            if (!((colbits[_cc >> 5] >> (_cc & 31)) & 1u)) { \
                _np = packHead(_kk, ((u32)(rr) << 12) | _cc); break; } \
        } \
        hptr[rr] = (unsigned char)_p; \
        if (_np) sheads[rr] = _np; else rs = (rr); \
    } \
} while (0)

// Cooperative exact rescan of one row (all 32 lanes participate).
#define COOP_RESCAN(ra_) do { \
    const float4* _rp = (const float4*)(scores + (size_t)(ra_) * NN); \
    u32 _bk = 0, _bc = 0xFFFu; \
    _Pragma("unroll 4") \
    for (int _q = 0; _q < 32; _q++) { \
        int _f = lane + _q * 32; \
        float4 _vv = _rp[_f]; \
        int _c0i = _f * 4; \
        float _arr[4] = { _vv.x, _vv.y, _vv.z, _vv.w }; \
        _Pragma("unroll") \
        for (int _j = 0; _j < 4; _j++) { \
            int _cc = _c0i + _j; \
            if (!((colbits[_cc >> 5] >> (_cc & 31)) & 1u)) { \
                u32 _kk = orderKey(_arr[_j]); \
                if (_kk > _bk) { _bk = _kk; _bc = (u32)_cc; } \
            } \
        } \
    } \
    u32 _mk2 = __reduce_max_sync(FULLMASK, _bk); \
    u32 _pc = (_bk == _mk2) ? (0x1000u - _bc) : 0u; \
    u32 _ps = __reduce_max_sync(FULLMASK, _pc); \
    if (lane == ((ra_) >> 5)) { \
        sheads[ra_] = _mk2 ? packHead(_mk2, ((u32)(ra_) << 12) | (0x1000u - _ps)) : 0ull; \
        hptr[ra_] = TCAND; \
    } \
} while (0)

#define REBUILD3(gc) do { \
    u64 x1 = 0, x2 = 0, x3 = 0; \
    const ulonglong2* _gp = (const ulonglong2*)(sheads + base + (gc) * 8); \
    _Pragma("unroll") \
    for (int _q = 0; _q < 4; _q++) { ulonglong2 _hh = _gp[_q]; INS3(_hh.x); INS3(_hh.y); } \
    sgt[(lane << 2) + (gc)] = x1; \
    sgt[128 + (lane << 2) + (gc)] = x2; \
    sgt[256 + (lane << 2) + (gc)] = x3; \
} while (0)

#define LANETOPS() do { \
    u64 x1 = 0, x2 = 0, x3 = 0; \
    _Pragma("unroll") \
    for (int _g = 0; _g < 4; _g++) { \
        INS3(sgt[(lane << 2) + _g]); \
        INS3(sgt[128 + (lane << 2) + _g]); \
        INS3(sgt[256 + (lane << 2) + _g]); \
    } \
    p1 = x1; p2 = x2; p3 = x3; \
} while (0)

// ---------------- K0: column-hit mask (bytes + bitmask) ------------------
__global__ void k0_colhit(const int* __restrict__ cont, const int* __restrict__ prev) {
    int tid = threadIdx.x;                 // 1024 threads
    #pragma unroll
    for (int k = 0; k < 4; k++) g_colhit[tid + k * 1024] = 0;
    if (tid < NN / 32) g_colbits[tid] = 0;
    __syncthreads();
    if (cont[tid]) {
        int c = prev[tid];
        g_colhit[c] = 1;                                  // benign races
        atomicOr(&g_colbits[c >> 5], 1u << (c & 31));
    }
}

// ---------------- K1: per-row rowmax, sumexp, top-4 masked candidates ----
__global__ void __launch_bounds__(256) k1_row(const float* __restrict__ scores,
                                              const int* __restrict__ cont) {
    const int r = blockIdx.x, tid = threadIdx.x, lane = tid & 31, warp = tid >> 5;
    __shared__ float wf[8];
    __shared__ u64   w64[8];
    __shared__ float s_bcast;
    __shared__ u64   s_win;

    const float4* row = (const float4*)(scores + (size_t)r * NN);
    const bool isCont = (cont[r] != 0);     // uniform per block

    float vals[16];
    int   fidx[4];
    #pragma unroll
    for (int k = 0; k < 4; k++) {
        int f = tid + k * 256; fidx[k] = f;
        float4 v = row[f];
        vals[k * 4 + 0] = v.x; vals[k * 4 + 1] = v.y;
        vals[k * 4 + 2] = v.z; vals[k * 4 + 3] = v.w;
    }

    float m = vals[0];
    #pragma unroll
    for (int e = 1; e < 16; e++) m = fmaxf(m, vals[e]);
    #pragma unroll
    for (int off = 16; off; off >>= 1) m = fmaxf(m, __shfl_xor_sync(FULLMASK, m, off));
    if (lane == 0) wf[warp] = m;
    __syncthreads();
    if (warp == 0) {
        float t = (lane < 8) ? wf[lane] : -3.4e38f;
        #pragma unroll
        for (int off = 4; off; off >>= 1) t = fmaxf(t, __shfl_xor_sync(FULLMASK, t, off));
        if (lane == 0) { s_bcast = t; g_rowmax[r] = t; }
    }
    __syncthreads();
    float rowmax = s_bcast;

    float s = 0.f;
    #pragma unroll
    for (int e = 0; e < 16; e++) s += __expf(vals[e] - rowmax);
    #pragma unroll
    for (int off = 16; off; off >>= 1) s += __shfl_xor_sync(FULLMASK, s, off);
    __syncthreads();
    if (lane == 0) wf[warp] = s;
    __syncthreads();
    if (warp == 0) {
        float t = (lane < 8) ? wf[lane] : 0.f;
        #pragma unroll
        for (int off = 4; off; off >>= 1) t += __shfl_xor_sync(FULLMASK, t, off);
        if (lane == 0) g_rowsum[r] = t;
    }

    if (isCont) {
        if (tid < TCAND) g_cand[r * TCAND + tid] = 0ull;
        return;
    }

    u64 pk[16];
    #pragma unroll
    for (int k = 0; k < 4; k++) {
        int4 h = ((const int4*)g_colhit)[fidx[k]];
        int hv[4] = { h.x, h.y, h.z, h.w };
        #pragma unroll
        for (int j = 0; j < 4; j++) {
            int col = fidx[k] * 4 + j;
            pk[k * 4 + j] = hv[j] ? 0ull
                : (((u64)orderKey(vals[k * 4 + j]) << 13) | (u64)(4096 - col));
        }
    }

    for (int round = 0; round < TCAND; round++) {
        u64 b = 0;
        #pragma unroll
        for (int e = 0; e < 16; e++) b = u64max(b, pk[e]);
        #pragma unroll
        for (int off = 16; off; off >>= 1)
            b = u64max(b, __shfl_xor_sync(FULLMASK, b, off));
        if (lane == 0) w64[warp] = b;
        __syncthreads();
        if (warp == 0) {
            u64 t = (lane < 8) ? w64[lane] : 0ull;
            #pragma unroll
            for (int off = 4; off; off >>= 1)
                t = u64max(t, __shfl_xor_sync(FULLMASK, t, off));
            if (lane == 0) {
                s_win = t;
                u32 key = (u32)(t >> 13);
                u32 col = 4096u - (u32)(t & 0x1FFFu);
                g_cand[r * TCAND + round] = t ? (((u64)key << 32) | col) : 0ull;
            }
        }
        __syncthreads();
        u64 wv = s_win;
        if (wv) {
            #pragma unroll
            for (int e = 0; e < 16; e++) if (pk[e] == wv) pk[e] = 0ull;
        }
    }
}

// ---------------- K2: global max + global sum -----------------------------
__global__ void __launch_bounds__(1024) k2_global() {
    int tid = threadIdx.x, lane = tid & 31, warp = tid >> 5;
    __shared__ float w[32];
    __shared__ float s_gm;
    float rm = g_rowmax[tid];
    float m = rm;
    #pragma unroll
    for (int off = 16; off; off >>= 1) m = fmaxf(m, __shfl_xor_sync(FULLMASK, m, off));
    if (lane == 0) w[warp] = m;
    __syncthreads();
    if (warp == 0) {
        float t = w[lane];
        #pragma unroll
        for (int off = 16; off; off >>= 1) t = fmaxf(t, __shfl_xor_sync(FULLMASK, t, off));
        if (lane == 0) s_gm = t;
    }
    __syncthreads();
    float gm = s_gm;
    float s = g_rowsum[tid] * __expf(rm - gm);
    #pragma unroll
    for (int off = 16; off; off >>= 1) s += __shfl_xor_sync(FULLMASK, s, off);
    __syncthreads();
    if (lane == 0) w[warp] = s;
    __syncthreads();
    if (warp == 0) {
        float t = w[lane];
        #pragma unroll
        for (int off = 16; off; off >>= 1) t += __shfl_xor_sync(FULLMASK, t, off);
        if (lane == 0) { g_gmax = gm; g_gsum = t; }
    }
}

// ---------------- K45: fused policy write + greedy assignment ------------
#define OFF_SHEADS 0
#define OFF_SCAND  8192
#define OFF_CLAIM  40960
#define OFF_SGT    57344
#define OFF_COLB   60416
#define OFF_HPTR   60928
#define OFF_MISC   61952
#define DSMEM      62464

__global__ void __launch_bounds__(1024, 1) k45_fused(
        const float* __restrict__ scores,
        const int* __restrict__ cont,
        const int* __restrict__ prev,
        float* __restrict__ out) {
    extern __shared__ char dyn[];
    const int tid = threadIdx.x;

    if (blockIdx.x < 512) {
        // ================= policy =================
        const float gm = g_gmax;
        const float inv = 1.0f / g_gsum;
        int i = blockIdx.x * 1024 + tid;
        const float4* p = (const float4*)scores;
        float4* o = (float4*)(out + MM);
        float4 a = p[i];
        float4 b = p[i + 524288];
        float4 ra, rb;
        ra.x = __expf(a.x - gm) * inv; ra.y = __expf(a.y - gm) * inv;
        ra.z = __expf(a.z - gm) * inv; ra.w = __expf(a.w - gm) * inv;
        rb.x = __expf(b.x - gm) * inv; rb.y = __expf(b.y - gm) * inv;
        rb.z = __expf(b.z - gm) * inv; rb.w = __expf(b.w - gm) * inv;
        o[i] = ra;
        o[i + 524288] = rb;
        return;
    }

    // ================= assignment (block 512) =================
    u64* sheads = (u64*)(dyn + OFF_SHEADS);
    u64* scand  = (u64*)(dyn + OFF_SCAND);
    u32* claimc = (u32*)(dyn + OFF_CLAIM);
    u64* sgt    = (u64*)(dyn + OFF_SGT);
    u32* colbits = (u32*)(dyn + OFF_COLB);
    unsigned char* hptr = (unsigned char*)(dyn + OFF_HPTR);
    int* misc = (int*)(dyn + OFF_MISC);
    float* out_act = out;

    #pragma unroll
    for (int k = 0; k < TCAND; k++) {
        int idx = tid + k * 1024;
        scand[idx] = g_cand[idx];
        claimc[idx] = 0;
    }
    if (tid < NN / 32) colbits[tid] = g_colbits[tid];
    {
        u64 c0 = g_cand[tid * TCAND];
        u32 key = (u32)(c0 >> 32);
        u32 col = (u32)c0 & 0xFFFu;
        sheads[tid] = key ? packHead(key, ((u32)tid << 12) | col) : 0ull;
    }
    hptr[tid] = 1;
    int myCont = cont[tid];
    out_act[tid] = myCont ? (float)prev[tid] : -1.0f;
    int K = __syncthreads_count(myCont == 0);
    if (tid == 0) misc[0] = K;
    __syncthreads();
    if (tid >= 32) return;

    const int lane = tid;
    const int base = lane * 32;
    const int K2 = misc[0];

    u64 p1, p2, p3;
    { REBUILD3(0); REBUILD3(1); REBUILD3(2); REBUILD3(3); }
    LANETOPS();

    int assigned = 0;
    int guard = 0;

    while (assigned < K2) {
        if (++guard > 16384) break;                  // safety (never hit)

        // ---- offers: lane's cached top-2 (distinct rows) ----
        bool l1 = (p1 != 0ull), l2 = (p2 != 0ull);
        u32 rc1 = 0x400000u - (u32)(p1 & 0x7FFFFFu);
        u32 rc2 = 0x400000u - (u32)(p2 & 0x7FFFFFu);
        int r1 = (int)(rc1 >> 12), c1 = (int)(rc1 & 0xFFFu);
        int r2 = (int)(rc2 >> 12), c2 = (int)(rc2 & 0xFFFu);

        // ---- validate offers: single inline pop per stale offer ----
        u64 o1 = p1, o2 = p2;
        bool ch1 = false, ch2 = false;
        int rsA = -1, rsB = -1;
        if (l1 && ((colbits[c1 >> 5] >> (c1 & 31)) & 1u)) { POPROW(r1, rsA); ch1 = true; }
        if (l2 && ((colbits[c2 >> 5] >> (c2 & 31)) & 1u)) { POPROW(r2, rsB); ch2 = true; }
        // rare: list-exhausted rows -> cooperative exact rescans
        for (;;) {
            int my = (rsA >= 0) ? rsA : rsB;
            u32 rb = __ballot_sync(FULLMASK, my >= 0);
            if (!rb) break;
            int ln = __ffs((int)rb) - 1;
            int ra = __shfl_sync(FULLMASK, my, ln);
            COOP_RESCAN(ra);
            if (lane == ln) { if (rsA == ra) rsA = -1; else rsB = -1; }
        }
        __syncwarp(FULLMASK);
        if (ch1) o1 = sheads[r1];
        if (ch2) o2 = sheads[r2];
        l1 = (o1 != 0ull); l2 = (o2 != 0ull);
        c1 = (int)((0x400000u - (u32)(o1 & 0x7FFFFFu)) & 0xFFFu);
        c2 = (int)((0x400000u - (u32)(o2 & 0x7FFFFFu)) & 0xFFFu);

        // ---- duplicate-column detection (all offers now valid) ----
        if (l1) atomicAdd(&claimc[c1], 1u);
        if (l2) atomicAdd(&claimc[c2], 1u);
        __syncwarp(FULLMASK);
        bool d1 = l1 && (claimc[c1] > 1u);
        bool d2 = l2 && (claimc[c2] > 1u);
        __syncwarp(FULLMASK);
        if (l1) claimc[c1] = 0;
        if (l2) claimc[c2] = 0;

        // ---- cutoff S = max(hidden bound p3, dup values) — no stale term ----
        u64 contrib = p3;
        if (d1) contrib = u64max(contrib, o1);
        if (d2) contrib = u64max(contrib, o2);
        u32 chi = (u32)(contrib >> 32);
        u32 mh = __reduce_max_sync(FULLMASK, chi);
        u32 clo = (chi == mh) ? (u32)contrib : 0u;
        u32 ml = __reduce_max_sync(FULLMASK, clo);
        u64 S = ((u64)mh << 32) | ml;

        // ---- parallel commits (exact greedy prefix) ----
        bool k1c = l1 && !d1 && (o1 > S);
        bool k2c = l2 && !d2 && (o2 > S);
        if (k1c) { atomicOr(&colbits[c1 >> 5], 1u << (c1 & 31));
                   out_act[r1] = (float)c1; sheads[r1] = 0ull; ch1 = true; }
        if (k2c) { atomicOr(&colbits[c2 >> 5], 1u << (c2 & 31));
                   out_act[r2] = (float)c2; sheads[r2] = 0ull; ch2 = true; }
        u32 cb1 = __ballot_sync(FULLMASK, k1c);
        u32 cb2 = __ballot_sync(FULLMASK, k2c);
        assigned += __popc(cb1) + __popc(cb2);
        __syncwarp(FULLMASK);

        // ---- fallback: no commits this batch ----
        if (!(cb1 | cb2)) {
            u64 lm = u64max(l1 ? o1 : 0ull, l2 ? o2 : 0ull);
            u32 fhi = (u32)(lm >> 32);
            u32 fmh = __reduce_max_sync(FULLMASK, fhi);
            u32 flo = (fhi == fmh) ? (u32)lm : 0u;
            u32 fml = __reduce_max_sync(FULLMASK, flo);
            u64 M = ((u64)fmh << 32) | fml;
            if (M >= S) {
                if (!M) break;                 // S==0 too: nothing left anywhere
                // M is the exact global max -> commit it (replicated stores)
                u32 rcf = 0x400000u - (u32)(M & 0x7FFFFFu);
                int rf = (int)(rcf >> 12), cf = (int)(rcf & 0xFFFu);
                u32 w = colbits[cf >> 5];              // uniform read
                colbits[cf >> 5] = w | (1u << (cf & 31));
                out_act[rf] = (float)cf;
                sheads[rf] = 0ull;
                assigned++;
                if (lane == (rf >> 5)) { if (rf == r1) ch1 = true; else ch2 = true; }
                __syncwarp(FULLMASK);
            } else {
                // stuck (very rare): cached p3 exceeds best valid offer.
                // Lanes with p3 > M validate all 32 rows in lockstep.
                bool stuck = (p3 > M);
                for (int j = 0; j < 32; j++) {
                    int rs = -1;
                    if (stuck) {
                        int rr = base + j;
                        u64 h = sheads[rr];
                        if (h) {
                            u32 hc = (0x400000u - (u32)(h & 0x7FFFFFu)) & 0xFFFu;
                            if ((colbits[hc >> 5] >> (hc & 31)) & 1u) POPROW(rr, rs);
                        }
                    }
                    u32 rb = __ballot_sync(FULLMASK, rs >= 0);
                    while (rb) {
                        int ln = __ffs((int)rb) - 1; rb &= rb - 1u;
                        int ra = __shfl_sync(FULLMASK, rs, ln);
                        COOP_RESCAN(ra);
                    }
                }
                __syncwarp(FULLMASK);
                if (stuck) {
                    REBUILD3(0); REBUILD3(1); REBUILD3(2); REBUILD3(3);
                    LANETOPS();
                    ch1 = ch2 = false;     // caches already fresh
                }
                continue;                  // retry with honest bounds
            }
        }

        // ---- refresh changed groups + lane tops ----
        if (ch1 || ch2) {
            int g1 = (r1 >> 3) & 3, g2 = (r2 >> 3) & 3;
            if (ch1) {
                switch (g1) { case 0: REBUILD3(0); break; case 1: REBUILD3(1); break;
                              case 2: REBUILD3(2); break; default: REBUILD3(3); break; }
            }
            if (ch2 && (!ch1 || g2 != g1)) {
                switch (g2) { case 0: REBUILD3(0); break; case 1: REBUILD3(1); break;
                              case 2: REBUILD3(2); break; default: REBUILD3(3); break; }
            }
            LANETOPS();
        }
    }
}

// ---------------- launch ---------------------------------------------------
extern "C" void kernel_launch(void* const* d_in, const int* in_sizes, int n_in,
                              void* d_out, int out_size) {
    const float* scores = (const float*)d_in[0];
    const int*   cont   = (const int*)d_in[1];
    const int*   prev   = (const int*)d_in[2];
    float* out = (float*)d_out;      // [0..1023] actions, [1024..] policy

    cudaFuncSetAttribute(k45_fused, cudaFuncAttributeMaxDynamicSharedMemorySize, DSMEM);

    k0_colhit<<<1, 1024>>>(cont, prev);
    k1_row<<<MM, 256>>>(scores, cont);
    k2_global<<<1, 1024>>>();
    k45_fused<<<513, 1024, DSMEM>>>(scores, cont, prev, out);
}

// round 14
// speedup vs baseline: 1.0212x; 1.0212x over previous
#include <cuda_runtime.h>
#include <cstdint>

#define MM 1024
#define NN 4096
#define TCAND 4
#define FULLMASK 0xffffffffu

typedef unsigned int       u32;
typedef unsigned long long u64;

// ---------------- device scratch (no allocations allowed) ----------------
__device__ int   g_colhit[NN];
__device__ u32   g_colbits[NN / 32];
__device__ float g_rowmax[MM];
__device__ float g_rowsum[MM];
__device__ u64   g_cand[MM * TCAND];   // per-row top-4: key<<32 | col
__device__ float g_gmax;
__device__ float g_gsum;

// Monotonic float -> uint32 ordering key (nonzero for all real floats).
__device__ __forceinline__ u32 orderKey(float v) {
    u32 b = __float_as_uint(v);
    return (b & 0x80000000u) ? ~b : (b | 0x80000000u);
}

// Packed head: key high, inverted flat index (row<<12|col) low 23 bits.
// u64 max == (max key, then smallest flat index) — exact reference tie-break.
__device__ __forceinline__ u64 packHead(u32 key, u32 rc) {
    return ((u64)key << 23) | (u64)(0x400000u - rc);
}

__device__ __forceinline__ u64 u64max(u64 a, u64 b) { return a > b ? a : b; }

// insert into descending top-3 (x1 >= x2 >= x3)
#define INS3(h) do { u64 _h = (h); \
    if (_h > x2) { if (_h > x1) { x3 = x2; x2 = x1; x1 = _h; } \
                   else         { x3 = x2; x2 = _h; } } \
    else if (_h > x3) x3 = _h; } while (0)

// insert into descending top-4 (t0 >= t1 >= t2 >= t3)
#define INS4(h) do { u64 _h = (h); \
    if (_h > t3) { \
        if (_h > t1) { \
            if (_h > t0) { t3 = t2; t2 = t1; t1 = t0; t0 = _h; } \
            else         { t3 = t2; t2 = t1; t1 = _h; } \
        } else { \
            if (_h > t2) { t3 = t2; t2 = _h; } \
            else         { t3 = _h; } \
        } \
    } } while (0)

// ---------------- K0: column-hit mask (bytes + bitmask) ------------------
__global__ void k0_colhit(const int* __restrict__ cont, const int* __restrict__ prev) {
    int tid = threadIdx.x;                 // 1024 threads
    #pragma unroll
    for (int k = 0; k < 4; k++) g_colhit[tid + k * 1024] = 0;
    if (tid < NN / 32) g_colbits[tid] = 0;
    __syncthreads();
    if (cont[tid]) {
        int c = prev[tid];
        g_colhit[c] = 1;                                  // benign races
        atomicOr(&g_colbits[c >> 5], 1u << (c & 31));
    }
}

// ---------------- K1: warp-per-row, streaming (online softmax + top-4) ---
// grid = 128 blocks x 256 threads; warp w owns row blockIdx*8 + w.
// Lane streams its 32 float4 (128 elements), keeping running (max,sum) and
// a lane-local top-4 of packed candidates. Pure warp shuffles at the end.
__global__ void __launch_bounds__(256) k1_row(const float* __restrict__ scores,
                                              const int* __restrict__ cont) {
    const int tid = threadIdx.x, lane = tid & 31, warp = tid >> 5;
    const int r = blockIdx.x * 8 + warp;
    const float4* row = (const float4*)(scores + (size_t)r * NN);
    const bool isCont = (cont[r] != 0);    // warp-uniform
    const int4* hit = (const int4*)g_colhit;

    float m = -3.4e38f;       // running max
    float s = 0.f;            // running sum of exp(x - m)
    u64 t0 = 0, t1 = 0, t2 = 0, t3 = 0;   // lane-local top-4 (packed)

    #pragma unroll 8
    for (int q = 0; q < 32; q++) {
        int f = q * 32 + lane;             // float4 index within row
        float4 v = row[f];
        // --- online softmax update ---
        float cm = fmaxf(fmaxf(v.x, v.y), fmaxf(v.z, v.w));
        float nm = fmaxf(m, cm);
        s = s * __expf(m - nm)
          + __expf(v.x - nm) + __expf(v.y - nm)
          + __expf(v.z - nm) + __expf(v.w - nm);
        m = nm;
        // --- masked candidate insertion ---
        if (!isCont) {
            int4 h = hit[f];
            int c0 = f * 4;
            if (!h.x) INS4(((u64)orderKey(v.x) << 13) | (u64)(4096 - c0));
            if (!h.y) INS4(((u64)orderKey(v.y) << 13) | (u64)(4096 - (c0 + 1)));
            if (!h.z) INS4(((u64)orderKey(v.z) << 13) | (u64)(4096 - (c0 + 2)));
            if (!h.w) INS4(((u64)orderKey(v.w) << 13) | (u64)(4096 - (c0 + 3)));
        }
    }

    // ---- warp-combine (max, sum) — all lanes end with row values ----
    float M = m;
    #pragma unroll
    for (int off = 16; off; off >>= 1) M = fmaxf(M, __shfl_xor_sync(FULLMASK, M, off));
    float sl = s * __expf(m - M);
    #pragma unroll
    for (int off = 16; off; off >>= 1) sl += __shfl_xor_sync(FULLMASK, sl, off);
    if (lane == 0) { g_rowmax[r] = M; g_rowsum[r] = sl; }

    if (isCont) {
        if (lane < TCAND) g_cand[r * TCAND + lane] = 0ull;
        return;
    }

    // ---- 4 rounds: warp u64-max over lane tops; remove winner ----
    #pragma unroll
    for (int round = 0; round < TCAND; round++) {
        u64 b = t0;
        #pragma unroll
        for (int off = 16; off; off >>= 1)
            b = u64max(b, __shfl_xor_sync(FULLMASK, b, off));
        if (lane == 0) {
            u32 key = (u32)(b >> 13);
            u32 col = 4096u - (u32)(b & 0x1FFFu);
            g_cand[r * TCAND + round] = b ? (((u64)key << 32) | col) : 0ull;
        }
        if (b && t0 == b) { t0 = t1; t1 = t2; t2 = t3; t3 = 0; }
    }
}

// ---------------- K2: global max + global sum (from row stats) -----------
__global__ void __launch_bounds__(1024) k2_global() {
    int tid = threadIdx.x, lane = tid & 31, warp = tid >> 5;
    __shared__ float w[32];
    __shared__ float s_gm;
    float rm = g_rowmax[tid];
    float m = rm;
    #pragma unroll
    for (int off = 16; off; off >>= 1) m = fmaxf(m, __shfl_xor_sync(FULLMASK, m, off));
    if (lane == 0) w[warp] = m;
    __syncthreads();
    if (warp == 0) {
        float t = w[lane];
        #pragma unroll
        for (int off = 16; off; off >>= 1) t = fmaxf(t, __shfl_xor_sync(FULLMASK, t, off));
        if (lane == 0) s_gm = t;
    }
    __syncthreads();
    float gm = s_gm;
    float s = g_rowsum[tid] * __expf(rm - gm);
    #pragma unroll
    for (int off = 16; off; off >>= 1) s += __shfl_xor_sync(FULLMASK, s, off);
    __syncthreads();
    if (lane == 0) w[warp] = s;
    __syncthreads();
    if (warp == 0) {
        float t = w[lane];
        #pragma unroll
        for (int off = 16; off; off >>= 1) t += __shfl_xor_sync(FULLMASK, t, off);
        if (lane == 0) { g_gmax = gm; g_gsum = t; }
    }
}

// ---------------- K45: fused policy write + greedy assignment ------------
// (verbatim Round-8/11 version — measured 82.4us total)
#define OFF_SHEADS 0
#define OFF_SCAND  8192
#define OFF_CLAIM  40960
#define OFF_SGT    57344
#define OFF_COLB   60416
#define OFF_HPTR   60928
#define OFF_MISC   61952
#define DSMEM      62464

__global__ void __launch_bounds__(1024, 1) k45_fused(
        const float* __restrict__ scores,
        const int* __restrict__ cont,
        const int* __restrict__ prev,
        float* __restrict__ out) {
    extern __shared__ char dyn[];
    const int tid = threadIdx.x;

    if (blockIdx.x < 512) {
        // ================= policy =================
        const float gm = g_gmax;
        const float inv = 1.0f / g_gsum;
        int i = blockIdx.x * 1024 + tid;
        const float4* p = (const float4*)scores;
        float4* o = (float4*)(out + MM);
        float4 a = p[i];
        float4 b = p[i + 524288];
        float4 ra, rb;
        ra.x = __expf(a.x - gm) * inv; ra.y = __expf(a.y - gm) * inv;
        ra.z = __expf(a.z - gm) * inv; ra.w = __expf(a.w - gm) * inv;
        rb.x = __expf(b.x - gm) * inv; rb.y = __expf(b.y - gm) * inv;
        rb.z = __expf(b.z - gm) * inv; rb.w = __expf(b.w - gm) * inv;
        o[i] = ra;
        o[i + 524288] = rb;
        return;
    }

    // ================= assignment (block 512) =================
    u64* sheads = (u64*)(dyn + OFF_SHEADS);
    u64* scand  = (u64*)(dyn + OFF_SCAND);
    u32* claimc = (u32*)(dyn + OFF_CLAIM);
    u64* sgt    = (u64*)(dyn + OFF_SGT);         // [0..127]=t1 [128..]=t2 [256..]=t3
    u32* colbits = (u32*)(dyn + OFF_COLB);
    unsigned char* hptr = (unsigned char*)(dyn + OFF_HPTR);
    int* misc = (int*)(dyn + OFF_MISC);
    float* out_act = out;

    // -------- prologue: full block builds shared state --------
    #pragma unroll
    for (int k = 0; k < TCAND; k++) {
        int idx = tid + k * 1024;
        scand[idx] = g_cand[idx];
        claimc[idx] = 0;
    }
    if (tid < NN / 32) colbits[tid] = g_colbits[tid];
    {
        u64 c0 = g_cand[tid * TCAND];
        u32 key = (u32)(c0 >> 32);
        u32 col = (u32)c0 & 0xFFFu;
        sheads[tid] = key ? packHead(key, ((u32)tid << 12) | col) : 0ull;
    }
    hptr[tid] = 1;
    int myCont = cont[tid];
    out_act[tid] = myCont ? (float)prev[tid] : -1.0f;
    int K = __syncthreads_count(myCont == 0);
    if (tid == 0) misc[0] = K;
    __syncthreads();
    if (tid >= 32) return;

    const int lane = tid;
    const int base = lane * 32;
    const int K2 = misc[0];

    // per-group top-3 cache + lane p1,p2,p3
    u64 p1, p2, p3;
    {
        #pragma unroll
        for (int g = 0; g < 4; g++) {
            u64 x1 = 0, x2 = 0, x3 = 0;
            const ulonglong2* gp = (const ulonglong2*)(sheads + base + g * 8);
            #pragma unroll
            for (int q = 0; q < 4; q++) { ulonglong2 hh = gp[q]; INS3(hh.x); INS3(hh.y); }
            sgt[(lane << 2) + g] = x1;
            sgt[128 + (lane << 2) + g] = x2;
            sgt[256 + (lane << 2) + g] = x3;
        }
        u64 x1 = 0, x2 = 0, x3 = 0;
        #pragma unroll
        for (int g = 0; g < 4; g++) {
            INS3(sgt[(lane << 2) + g]);
            INS3(sgt[128 + (lane << 2) + g]);
            INS3(sgt[256 + (lane << 2) + g]);
        }
        p1 = x1; p2 = x2; p3 = x3;
    }

    int assigned = 0;
    int guard = 0;

    while (assigned < K2) {
        if (++guard > 16384) break;                  // safety (never hit)

        // ---- candidates: lane's top-2 heads (distinct rows) ----
        bool l1 = (p1 != 0ull), l2 = (p2 != 0ull);
        u32 rc1 = 0x400000u - (u32)(p1 & 0x7FFFFFu);
        u32 rc2 = 0x400000u - (u32)(p2 & 0x7FFFFFu);
        int r1 = (int)(rc1 >> 12), c1 = (int)(rc1 & 0xFFFu);
        int r2 = (int)(rc2 >> 12), c2 = (int)(rc2 & 0xFFFu);

        // ---- stale at batch start ----
        bool s1 = l1 && ((colbits[c1 >> 5] >> (c1 & 31)) & 1u);
        bool s2 = l2 && ((colbits[c2 >> 5] >> (c2 & 31)) & 1u);

        // ---- dup detection among live offers ----
        if (l1 && !s1) atomicAdd(&claimc[c1], 1u);
        if (l2 && !s2) atomicAdd(&claimc[c2], 1u);
        __syncwarp(FULLMASK);
        bool d1 = l1 && !s1 && (claimc[c1] > 1u);
        bool d2 = l2 && !s2 && (claimc[c2] > 1u);
        __syncwarp(FULLMASK);
        if (l1 && !s1) claimc[c1] = 0;
        if (l2 && !s2) claimc[c2] = 0;

        // ---- cutoff S = max(hidden bound p3, stale/dup offer values) ----
        u64 contrib = p3;
        if (s1 || d1) contrib = u64max(contrib, p1);
        if (s2 || d2) contrib = u64max(contrib, p2);
        u32 chi = (u32)(contrib >> 32);
        u32 mh = __reduce_max_sync(FULLMASK, chi);
        u32 clo = (chi == mh) ? (u32)contrib : 0u;
        u32 ml = __reduce_max_sync(FULLMASK, clo);
        u64 S = ((u64)mh << 32) | ml;

        // ---- parallel commits ----
        bool k1c = l1 && !s1 && !d1 && (p1 > S);
        bool k2c = l2 && !s2 && !d2 && (p2 > S);
        if (k1c) { atomicOr(&colbits[c1 >> 5], 1u << (c1 & 31));
                   out_act[r1] = (float)c1; sheads[r1] = 0ull; }
        if (k2c) { atomicOr(&colbits[c2 >> 5], 1u << (c2 & 31));
                   out_act[r2] = (float)c2; sheads[r2] = 0ull; }
        u32 cb = __ballot_sync(FULLMASK, k1c) ;
        u32 cb2 = __ballot_sync(FULLMASK, k2c);
        assigned += __popc(cb) + __popc(cb2);
        __syncwarp(FULLMASK);

        // ---- fallback single-commit when batch was empty ----
        if (!(cb | cb2)) {
            u32 key = (u32)(p1 >> 23);
            u32 mk = __reduce_max_sync(FULLMASK, key);
            if (mk == 0) break;                       // nothing left (uniform)
            u32 cnd = (key == mk) ? (u32)(p1 & 0x7FFFFFu) : 0u;
            u32 sel = __reduce_max_sync(FULLMASK, cnd);
            u32 rcf = 0x400000u - sel;
            int af = (int)(rcf >> 12), tf = (int)(rcf & 0xFFFu);
            u32 w = colbits[tf >> 5];                 // uniform read
            if (!((w >> (tf & 31)) & 1u)) {
                colbits[tf >> 5] = w | (1u << (tf & 31));   // replicated
                out_act[af] = (float)tf;
                sheads[af] = 0ull;
                assigned++;
                if (lane == (af >> 5)) k1c = true;    // af == r1 for owner
            }
            // if stale: pop phase below handles it
        }

        // ---- pop phase: recheck my two offered rows vs updated colbits ----
        bool ch1 = k1c, ch2 = k2c;
        int rsA = -1, rsB = -1;
        if (l1) {
            u64 h = sheads[r1];
            if (h) {
                u32 hc = (0x400000u - (u32)(h & 0x7FFFFFu)) & 0xFFFu;
                if ((colbits[hc >> 5] >> (hc & 31)) & 1u) {
                    int p = hptr[r1]; u64 np = 0ull;
                    if (p < TCAND) {
                        while (p < TCAND) {
                            u64 cd = scand[(r1 << 2) + p]; p++;
                            u32 kk = (u32)(cd >> 32);
                            if (!kk) { p = TCAND; break; }
                            u32 cc = (u32)cd & 0xFFFu;
                            if (!((colbits[cc >> 5] >> (cc & 31)) & 1u)) {
                                np = packHead(kk, ((u32)r1 << 12) | cc); break;
                            }
                        }
                        hptr[r1] = (unsigned char)p;
                    }
                    if (np) sheads[r1] = np; else rsA = r1;
                    ch1 = true;
                }
            }
        }
        if (l2) {
            u64 h = sheads[r2];
            if (h) {
                u32 hc = (0x400000u - (u32)(h & 0x7FFFFFu)) & 0xFFFu;
                if ((colbits[hc >> 5] >> (hc & 31)) & 1u) {
                    int p = hptr[r2]; u64 np = 0ull;
                    if (p < TCAND) {
                        while (p < TCAND) {
                            u64 cd = scand[(r2 << 2) + p]; p++;
                            u32 kk = (u32)(cd >> 32);
                            if (!kk) { p = TCAND; break; }
                            u32 cc = (u32)cd & 0xFFFu;
                            if (!((colbits[cc >> 5] >> (cc & 31)) & 1u)) {
                                np = packHead(kk, ((u32)r2 << 12) | cc); break;
                            }
                        }
                        hptr[r2] = (unsigned char)p;
                    }
                    if (np) sheads[r2] = np; else rsB = r2;
                    ch2 = true;
                }
            }
        }

        // ---- rare: warp-cooperative exact rescans (list exhausted) ----
        for (;;) {
            int my = (rsA >= 0) ? rsA : rsB;
            u32 rb = __ballot_sync(FULLMASK, my >= 0);
            if (!rb) break;
            int ln = __ffs((int)rb) - 1;
            int ra = __shfl_sync(FULLMASK, my, ln);
            const float4* rp = (const float4*)(scores + (size_t)ra * NN);
            u32 bk = 0, bc = 0xFFFu;
            #pragma unroll 4
            for (int q = 0; q < 32; q++) {
                int f = lane + q * 32;
                float4 vv = rp[f];
                int c0i = f * 4;
                float arr[4] = { vv.x, vv.y, vv.z, vv.w };
                #pragma unroll
                for (int j = 0; j < 4; j++) {
                    int cc = c0i + j;
                    if (!((colbits[cc >> 5] >> (cc & 31)) & 1u)) {
                        u32 kk = orderKey(arr[j]);
                        if (kk > bk) { bk = kk; bc = (u32)cc; }
                    }
                }
            }
            u32 mk2 = __reduce_max_sync(FULLMASK, bk);
            u32 pc = (bk == mk2) ? (0x1000u - bc) : 0u;
            u32 ps = __reduce_max_sync(FULLMASK, pc);
            if (lane == ln) {
                sheads[ra] = mk2 ? packHead(mk2, ((u32)ra << 12) | (0x1000u - ps)) : 0ull;
                hptr[ra] = TCAND;
                if (rsA == ra) rsA = -1; else rsB = -1;
            }
        }
        __syncwarp(FULLMASK);

        // ---- refresh changed groups + lane tops ----
        if (ch1 || ch2) {
            int g1 = (r1 >> 3) & 3, g2 = (r2 >> 3) & 3;
            if (ch1) {
                u64 x1 = 0, x2 = 0, x3 = 0;
                const ulonglong2* gp = (const ulonglong2*)(sheads + base + g1 * 8);
                #pragma unroll
                for (int q = 0; q < 4; q++) { ulonglong2 hh = gp[q]; INS3(hh.x); INS3(hh.y); }
                sgt[(lane << 2) + g1] = x1;
                sgt[128 + (lane << 2) + g1] = x2;
                sgt[256 + (lane << 2) + g1] = x3;
            }
            if (ch2 && (!ch1 || g2 != g1)) {
                u64 x1 = 0, x2 = 0, x3 = 0;
                const ulonglong2* gp = (const ulonglong2*)(sheads + base + g2 * 8);
                #pragma unroll
                for (int q = 0; q < 4; q++) { ulonglong2 hh = gp[q]; INS3(hh.x); INS3(hh.y); }
                sgt[(lane << 2) + g2] = x1;
                sgt[128 + (lane << 2) + g2] = x2;
                sgt[256 + (lane << 2) + g2] = x3;
            }
            u64 x1 = 0, x2 = 0, x3 = 0;
            #pragma unroll
            for (int g = 0; g < 4; g++) {
                INS3(sgt[(lane << 2) + g]);
                INS3(sgt[128 + (lane << 2) + g]);
                INS3(sgt[256 + (lane << 2) + g]);
            }
            p1 = x1; p2 = x2; p3 = x3;
        }
    }
}

// ---------------- launch ---------------------------------------------------
extern "C" void kernel_launch(void* const* d_in, const int* in_sizes, int n_in,
                              void* d_out, int out_size) {
    const float* scores = (const float*)d_in[0];
    const int*   cont   = (const int*)d_in[1];
    const int*   prev   = (const int*)d_in[2];
    float* out = (float*)d_out;      // [0..1023] actions, [1024..] policy

    cudaFuncSetAttribute(k45_fused, cudaFuncAttributeMaxDynamicSharedMemorySize, DSMEM);

    k0_colhit<<<1, 1024>>>(cont, prev);
    k1_row<<<MM / 8, 256>>>(scores, cont);
    k2_global<<<1, 1024>>>();
    k45_fused<<<513, 1024, DSMEM>>>(scores, cont, prev, out);
}

// round 15
// speedup vs baseline: 1.2298x; 1.2043x over previous
#include <cuda_runtime.h>
#include <cstdint>

#define MM 1024
#define NN 4096
#define TCAND 4
#define FULLMASK 0xffffffffu

typedef unsigned int       u32;
typedef unsigned long long u64;

// ---------------- device scratch (no allocations allowed) ----------------
__device__ int   g_colhit[NN];
__device__ u32   g_colbits[NN / 32];
__device__ float g_rowmax[MM];
__device__ float g_rowsum[MM];
__device__ u64   g_cand[MM * TCAND];   // per-row top-4: key<<32 | col
__device__ float g_gmax;
__device__ float g_gsum;

// Monotonic float -> uint32 ordering key (nonzero for all real floats).
__device__ __forceinline__ u32 orderKey(float v) {
    u32 b = __float_as_uint(v);
    return (b & 0x80000000u) ? ~b : (b | 0x80000000u);
}

// Packed head: key high, inverted flat index (row<<12|col) low 23 bits.
// u64 max == (max key, then smallest flat index) — exact reference tie-break.
__device__ __forceinline__ u64 packHead(u32 key, u32 rc) {
    return ((u64)key << 23) | (u64)(0x400000u - rc);
}

__device__ __forceinline__ u64 u64max(u64 a, u64 b) { return a > b ? a : b; }

// insert into descending top-3 (x1 >= x2 >= x3)
#define INS3(h) do { u64 _h = (h); \
    if (_h > x2) { if (_h > x1) { x3 = x2; x2 = x1; x1 = _h; } \
                   else         { x3 = x2; x2 = _h; } } \
    else if (_h > x3) x3 = _h; } while (0)

// ---------------- K0: column-hit mask (bytes + bitmask) ------------------
__global__ void k0_colhit(const int* __restrict__ cont, const int* __restrict__ prev) {
    int tid = threadIdx.x;                 // 1024 threads
    #pragma unroll
    for (int k = 0; k < 4; k++) g_colhit[tid + k * 1024] = 0;
    if (tid < NN / 32) g_colbits[tid] = 0;
    __syncthreads();
    if (cont[tid]) {
        int c = prev[tid];
        g_colhit[c] = 1;                                  // benign races
        atomicOr(&g_colbits[c >> 5], 1u << (c & 31));
    }
}

// ---------------- K1: per-row rowmax, sumexp, top-4 masked candidates ----
// Block-per-row (proven structure); candidate rounds use warp-local top-4
// extraction (no barriers) + one merge by warp 0 (1 barrier total).
__global__ void __launch_bounds__(256) k1_row(const float* __restrict__ scores,
                                              const int* __restrict__ cont) {
    const int r = blockIdx.x, tid = threadIdx.x, lane = tid & 31, warp = tid >> 5;
    __shared__ float wf[8];
    __shared__ float s_bcast;
    __shared__ u64   wtop[32];             // 8 warps x 4 candidates

    const float4* row = (const float4*)(scores + (size_t)r * NN);
    const bool isCont = (cont[r] != 0);    // uniform per block

    float vals[16];
    int   fidx[4];
    #pragma unroll
    for (int k = 0; k < 4; k++) {
        int f = tid + k * 256; fidx[k] = f;
        float4 v = row[f];
        vals[k * 4 + 0] = v.x; vals[k * 4 + 1] = v.y;
        vals[k * 4 + 2] = v.z; vals[k * 4 + 3] = v.w;
    }

    // ---- raw row max ----
    float m = vals[0];
    #pragma unroll
    for (int e = 1; e < 16; e++) m = fmaxf(m, vals[e]);
    #pragma unroll
    for (int off = 16; off; off >>= 1) m = fmaxf(m, __shfl_xor_sync(FULLMASK, m, off));
    if (lane == 0) wf[warp] = m;
    __syncthreads();
    if (warp == 0) {
        float t = (lane < 8) ? wf[lane] : -3.4e38f;
        #pragma unroll
        for (int off = 4; off; off >>= 1) t = fmaxf(t, __shfl_xor_sync(FULLMASK, t, off));
        if (lane == 0) { s_bcast = t; g_rowmax[r] = t; }
    }
    __syncthreads();
    float rowmax = s_bcast;

    // ---- row sumexp (stable at rowmax) ----
    float s = 0.f;
    #pragma unroll
    for (int e = 0; e < 16; e++) s += __expf(vals[e] - rowmax);
    #pragma unroll
    for (int off = 16; off; off >>= 1) s += __shfl_xor_sync(FULLMASK, s, off);
    __syncthreads();
    if (lane == 0) wf[warp] = s;
    __syncthreads();
    if (warp == 0) {
        float t = (lane < 8) ? wf[lane] : 0.f;
        #pragma unroll
        for (int off = 4; off; off >>= 1) t += __shfl_xor_sync(FULLMASK, t, off);
        if (lane == 0) g_rowsum[r] = t;
    }

    // ---- continuing rows: empty candidate list, done (uniform branch) ----
    if (isCont) {
        if (tid < TCAND) g_cand[r * TCAND + tid] = 0ull;
        return;
    }

    // ---- pack once: key<<13 | (4096-col); u64 max == exact tie-break ----
    u64 pk[16];
    #pragma unroll
    for (int k = 0; k < 4; k++) {
        int4 h = ((const int4*)g_colhit)[fidx[k]];
        int hv[4] = { h.x, h.y, h.z, h.w };
        #pragma unroll
        for (int j = 0; j < 4; j++) {
            int col = fidx[k] * 4 + j;
            pk[k * 4 + j] = hv[j] ? 0ull
                : (((u64)orderKey(vals[k * 4 + j]) << 13) | (u64)(4096 - col));
        }
    }

    // ---- warp-local top-4 (4 shuffle rounds, no barriers) ----
    #pragma unroll
    for (int round = 0; round < TCAND; round++) {
        u64 b = 0;
        #pragma unroll
        for (int e = 0; e < 16; e++) b = u64max(b, pk[e]);
        #pragma unroll
        for (int off = 16; off; off >>= 1)
            b = u64max(b, __shfl_xor_sync(FULLMASK, b, off));
        if (lane == 0) wtop[warp * 4 + round] = b;
        if (b) {
            #pragma unroll
            for (int e = 0; e < 16; e++) if (pk[e] == b) pk[e] = 0ull;
        }
    }
    __syncthreads();                        // single barrier

    // ---- warp 0 merges 32 candidates (one per lane) into row top-4 ----
    if (warp == 0) {
        u64 mine = wtop[lane];
        #pragma unroll
        for (int round = 0; round < TCAND; round++) {
            u64 b = mine;
            #pragma unroll
            for (int off = 16; off; off >>= 1)
                b = u64max(b, __shfl_xor_sync(FULLMASK, b, off));
            if (lane == 0) {
                u32 key = (u32)(b >> 13);
                u32 col = 4096u - (u32)(b & 0x1FFFu);
                g_cand[r * TCAND + round] = b ? (((u64)key << 32) | col) : 0ull;
            }
            if (b && mine == b) mine = 0ull;
        }
    }
}

// ---------------- K2: global max + global sum (from row stats) -----------
__global__ void __launch_bounds__(1024) k2_global() {
    int tid = threadIdx.x, lane = tid & 31, warp = tid >> 5;
    __shared__ float w[32];
    __shared__ float s_gm;
    float rm = g_rowmax[tid];
    float m = rm;
    #pragma unroll
    for (int off = 16; off; off >>= 1) m = fmaxf(m, __shfl_xor_sync(FULLMASK, m, off));
    if (lane == 0) w[warp] = m;
    __syncthreads();
    if (warp == 0) {
        float t = w[lane];
        #pragma unroll
        for (int off = 16; off; off >>= 1) t = fmaxf(t, __shfl_xor_sync(FULLMASK, t, off));
        if (lane == 0) s_gm = t;
    }
    __syncthreads();
    float gm = s_gm;
    float s = g_rowsum[tid] * __expf(rm - gm);
    #pragma unroll
    for (int off = 16; off; off >>= 1) s += __shfl_xor_sync(FULLMASK, s, off);
    __syncthreads();
    if (lane == 0) w[warp] = s;
    __syncthreads();
    if (warp == 0) {
        float t = w[lane];
        #pragma unroll
        for (int off = 16; off; off >>= 1) t += __shfl_xor_sync(FULLMASK, t, off);
        if (lane == 0) { g_gmax = gm; g_gsum = t; }
    }
}

// ---------------- K45: fused policy write + greedy assignment ------------
// (verbatim Round-8/11 version — measured 82.4us total)
#define OFF_SHEADS 0
#define OFF_SCAND  8192
#define OFF_CLAIM  40960
#define OFF_SGT    57344
#define OFF_COLB   60416
#define OFF_HPTR   60928
#define OFF_MISC   61952
#define DSMEM      62464

__global__ void __launch_bounds__(1024, 1) k45_fused(
        const float* __restrict__ scores,
        const int* __restrict__ cont,
        const int* __restrict__ prev,
        float* __restrict__ out) {
    extern __shared__ char dyn[];
    const int tid = threadIdx.x;

    if (blockIdx.x < 512) {
        // ================= policy =================
        const float gm = g_gmax;
        const float inv = 1.0f / g_gsum;
        int i = blockIdx.x * 1024 + tid;
        const float4* p = (const float4*)scores;
        float4* o = (float4*)(out + MM);
        float4 a = p[i];
        float4 b = p[i + 524288];
        float4 ra, rb;
        ra.x = __expf(a.x - gm) * inv; ra.y = __expf(a.y - gm) * inv;
        ra.z = __expf(a.z - gm) * inv; ra.w = __expf(a.w - gm) * inv;
        rb.x = __expf(b.x - gm) * inv; rb.y = __expf(b.y - gm) * inv;
        rb.z = __expf(b.z - gm) * inv; rb.w = __expf(b.w - gm) * inv;
        o[i] = ra;
        o[i + 524288] = rb;
        return;
    }

    // ================= assignment (block 512) =================
    u64* sheads = (u64*)(dyn + OFF_SHEADS);
    u64* scand  = (u64*)(dyn + OFF_SCAND);
    u32* claimc = (u32*)(dyn + OFF_CLAIM);
    u64* sgt    = (u64*)(dyn + OFF_SGT);         // [0..127]=t1 [128..]=t2 [256..]=t3
    u32* colbits = (u32*)(dyn + OFF_COLB);
    unsigned char* hptr = (unsigned char*)(dyn + OFF_HPTR);
    int* misc = (int*)(dyn + OFF_MISC);
    float* out_act = out;

    // -------- prologue: full block builds shared state --------
    #pragma unroll
    for (int k = 0; k < TCAND; k++) {
        int idx = tid + k * 1024;
        scand[idx] = g_cand[idx];
        claimc[idx] = 0;
    }
    if (tid < NN / 32) colbits[tid] = g_colbits[tid];
    {
        u64 c0 = g_cand[tid * TCAND];
        u32 key = (u32)(c0 >> 32);
        u32 col = (u32)c0 & 0xFFFu;
        sheads[tid] = key ? packHead(key, ((u32)tid << 12) | col) : 0ull;
    }
    hptr[tid] = 1;
    int myCont = cont[tid];
    out_act[tid] = myCont ? (float)prev[tid] : -1.0f;
    int K = __syncthreads_count(myCont == 0);
    if (tid == 0) misc[0] = K;
    __syncthreads();
    if (tid >= 32) return;

    const int lane = tid;
    const int base = lane * 32;
    const int K2 = misc[0];

    // per-group top-3 cache + lane p1,p2,p3
    u64 p1, p2, p3;
    {
        #pragma unroll
        for (int g = 0; g < 4; g++) {
            u64 x1 = 0, x2 = 0, x3 = 0;
            const ulonglong2* gp = (const ulonglong2*)(sheads + base + g * 8);
            #pragma unroll
            for (int q = 0; q < 4; q++) { ulonglong2 hh = gp[q]; INS3(hh.x); INS3(hh.y); }
            sgt[(lane << 2) + g] = x1;
            sgt[128 + (lane << 2) + g] = x2;
            sgt[256 + (lane << 2) + g] = x3;
        }
        u64 x1 = 0, x2 = 0, x3 = 0;
        #pragma unroll
        for (int g = 0; g < 4; g++) {
            INS3(sgt[(lane << 2) + g]);
            INS3(sgt[128 + (lane << 2) + g]);
            INS3(sgt[256 + (lane << 2) + g]);
        }
        p1 = x1; p2 = x2; p3 = x3;
    }

    int assigned = 0;
    int guard = 0;

    while (assigned < K2) {
        if (++guard > 16384) break;                  // safety (never hit)

        // ---- candidates: lane's top-2 heads (distinct rows) ----
        bool l1 = (p1 != 0ull), l2 = (p2 != 0ull);
        u32 rc1 = 0x400000u - (u32)(p1 & 0x7FFFFFu);
        u32 rc2 = 0x400000u - (u32)(p2 & 0x7FFFFFu);
        int r1 = (int)(rc1 >> 12), c1 = (int)(rc1 & 0xFFFu);
        int r2 = (int)(rc2 >> 12), c2 = (int)(rc2 & 0xFFFu);

        // ---- stale at batch start ----
        bool s1 = l1 && ((colbits[c1 >> 5] >> (c1 & 31)) & 1u);
        bool s2 = l2 && ((colbits[c2 >> 5] >> (c2 & 31)) & 1u);

        // ---- dup detection among live offers ----
        if (l1 && !s1) atomicAdd(&claimc[c1], 1u);
        if (l2 && !s2) atomicAdd(&claimc[c2], 1u);
        __syncwarp(FULLMASK);
        bool d1 = l1 && !s1 && (claimc[c1] > 1u);
        bool d2 = l2 && !s2 && (claimc[c2] > 1u);
        __syncwarp(FULLMASK);
        if (l1 && !s1) claimc[c1] = 0;
        if (l2 && !s2) claimc[c2] = 0;

        // ---- cutoff S = max(hidden bound p3, stale/dup offer values) ----
        u64 contrib = p3;
        if (s1 || d1) contrib = u64max(contrib, p1);
        if (s2 || d2) contrib = u64max(contrib, p2);
        u32 chi = (u32)(contrib >> 32);
        u32 mh = __reduce_max_sync(FULLMASK, chi);
        u32 clo = (chi == mh) ? (u32)contrib : 0u;
        u32 ml = __reduce_max_sync(FULLMASK, clo);
        u64 S = ((u64)mh << 32) | ml;

        // ---- parallel commits ----
        bool k1c = l1 && !s1 && !d1 && (p1 > S);
        bool k2c = l2 && !s2 && !d2 && (p2 > S);
        if (k1c) { atomicOr(&colbits[c1 >> 5], 1u << (c1 & 31));
                   out_act[r1] = (float)c1; sheads[r1] = 0ull; }
        if (k2c) { atomicOr(&colbits[c2 >> 5], 1u << (c2 & 31));
                   out_act[r2] = (float)c2; sheads[r2] = 0ull; }
        u32 cb = __ballot_sync(FULLMASK, k1c) ;
        u32 cb2 = __ballot_sync(FULLMASK, k2c);
        assigned += __popc(cb) + __popc(cb2);
        __syncwarp(FULLMASK);

        // ---- fallback single-commit when batch was empty ----
        if (!(cb | cb2)) {
            u32 key = (u32)(p1 >> 23);
            u32 mk = __reduce_max_sync(FULLMASK, key);
            if (mk == 0) break;                       // nothing left (uniform)
            u32 cnd = (key == mk) ? (u32)(p1 & 0x7FFFFFu) : 0u;
            u32 sel = __reduce_max_sync(FULLMASK, cnd);
            u32 rcf = 0x400000u - sel;
            int af = (int)(rcf >> 12), tf = (int)(rcf & 0xFFFu);
            u32 w = colbits[tf >> 5];                 // uniform read
            if (!((w >> (tf & 31)) & 1u)) {
                colbits[tf >> 5] = w | (1u << (tf & 31));   // replicated
                out_act[af] = (float)tf;
                sheads[af] = 0ull;
                assigned++;
                if (lane == (af >> 5)) k1c = true;    // af == r1 for owner
            }
            // if stale: pop phase below handles it
        }

        // ---- pop phase: recheck my two offered rows vs updated colbits ----
        bool ch1 = k1c, ch2 = k2c;
        int rsA = -1, rsB = -1;
        if (l1) {
            u64 h = sheads[r1];
            if (h) {
                u32 hc = (0x400000u - (u32)(h & 0x7FFFFFu)) & 0xFFFu;
                if ((colbits[hc >> 5] >> (hc & 31)) & 1u) {
                    int p = hptr[r1]; u64 np = 0ull;
                    if (p < TCAND) {
                        while (p < TCAND) {
                            u64 cd = scand[(r1 << 2) + p]; p++;
                            u32 kk = (u32)(cd >> 32);
                            if (!kk) { p = TCAND; break; }
                            u32 cc = (u32)cd & 0xFFFu;
                            if (!((colbits[cc >> 5] >> (cc & 31)) & 1u)) {
                                np = packHead(kk, ((u32)r1 << 12) | cc); break;
                            }
                        }
                        hptr[r1] = (unsigned char)p;
                    }
                    if (np) sheads[r1] = np; else rsA = r1;
                    ch1 = true;
                }
            }
        }
        if (l2) {
            u64 h = sheads[r2];
            if (h) {
                u32 hc = (0x400000u - (u32)(h & 0x7FFFFFu)) & 0xFFFu;
                if ((colbits[hc >> 5] >> (hc & 31)) & 1u) {
                    int p = hptr[r2]; u64 np = 0ull;
                    if (p < TCAND) {
                        while (p < TCAND) {
                            u64 cd = scand[(r2 << 2) + p]; p++;
                            u32 kk = (u32)(cd >> 32);
                            if (!kk) { p = TCAND; break; }
                            u32 cc = (u32)cd & 0xFFFu;
                            if (!((colbits[cc >> 5] >> (cc & 31)) & 1u)) {
                                np = packHead(kk, ((u32)r2 << 12) | cc); break;
                            }
                        }
                        hptr[r2] = (unsigned char)p;
                    }
                    if (np) sheads[r2] = np; else rsB = r2;
                    ch2 = true;
                }
            }
        }

        // ---- rare: warp-cooperative exact rescans (list exhausted) ----
        for (;;) {
            int my = (rsA >= 0) ? rsA : rsB;
            u32 rb = __ballot_sync(FULLMASK, my >= 0);
            if (!rb) break;
            int ln = __ffs((int)rb) - 1;
            int ra = __shfl_sync(FULLMASK, my, ln);
            const float4* rp = (const float4*)(scores + (size_t)ra * NN);
            u32 bk = 0, bc = 0xFFFu;
            #pragma unroll 4
            for (int q = 0; q < 32; q++) {
                int f = lane + q * 32;
                float4 vv = rp[f];
                int c0i = f * 4;
                float arr[4] = { vv.x, vv.y, vv.z, vv.w };
                #pragma unroll
                for (int j = 0; j < 4; j++) {
                    int cc = c0i + j;
                    if (!((colbits[cc >> 5] >> (cc & 31)) & 1u)) {
                        u32 kk = orderKey(arr[j]);
                        if (kk > bk) { bk = kk; bc = (u32)cc; }
                    }
                }
            }
            u32 mk2 = __reduce_max_sync(FULLMASK, bk);
            u32 pc = (bk == mk2) ? (0x1000u - bc) : 0u;
            u32 ps = __reduce_max_sync(FULLMASK, pc);
            if (lane == ln) {
                sheads[ra] = mk2 ? packHead(mk2, ((u32)ra << 12) | (0x1000u - ps)) : 0ull;
                hptr[ra] = TCAND;
                if (rsA == ra) rsA = -1; else rsB = -1;
            }
        }
        __syncwarp(FULLMASK);

        // ---- refresh changed groups + lane tops ----
        if (ch1 || ch2) {
            int g1 = (r1 >> 3) & 3, g2 = (r2 >> 3) & 3;
            if (ch1) {
                u64 x1 = 0, x2 = 0, x3 = 0;
                const ulonglong2* gp = (const ulonglong2*)(sheads + base + g1 * 8);
                #pragma unroll
                for (int q = 0; q < 4; q++) { ulonglong2 hh = gp[q]; INS3(hh.x); INS3(hh.y); }
                sgt[(lane << 2) + g1] = x1;
                sgt[128 + (lane << 2) + g1] = x2;
                sgt[256 + (lane << 2) + g1] = x3;
            }
            if (ch2 && (!ch1 || g2 != g1)) {
                u64 x1 = 0, x2 = 0, x3 = 0;
                const ulonglong2* gp = (const ulonglong2*)(sheads + base + g2 * 8);
                #pragma unroll
                for (int q = 0; q < 4; q++) { ulonglong2 hh = gp[q]; INS3(hh.x); INS3(hh.y); }
                sgt[(lane << 2) + g2] = x1;
                sgt[128 + (lane << 2) + g2] = x2;
                sgt[256 + (lane << 2) + g2] = x3;
            }
            u64 x1 = 0, x2 = 0, x3 = 0;
            #pragma unroll
            for (int g = 0; g < 4; g++) {
                INS3(sgt[(lane << 2) + g]);
                INS3(sgt[128 + (lane << 2) + g]);
                INS3(sgt[256 + (lane << 2) + g]);
            }
            p1 = x1; p2 = x2; p3 = x3;
        }
    }
}

// ---------------- launch ---------------------------------------------------
extern "C" void kernel_launch(void* const* d_in, const int* in_sizes, int n_in,
                              void* d_out, int out_size) {
    const float* scores = (const float*)d_in[0];
    const int*   cont   = (const int*)d_in[1];
    const int*   prev   = (const int*)d_in[2];
    float* out = (float*)d_out;      // [0..1023] actions, [1024..] policy

    cudaFuncSetAttribute(k45_fused, cudaFuncAttributeMaxDynamicSharedMemorySize, DSMEM);

    k0_colhit<<<1, 1024>>>(cont, prev);
    k1_row<<<MM, 256>>>(scores, cont);
    k2_global<<<1, 1024>>>();
    k45_fused<<<513, 1024, DSMEM>>>(scores, cont, prev, out);
}

// round 16
// speedup vs baseline: 1.4518x; 1.1805x over previous
#include <cuda_runtime.h>
#include <cstdint>

#define MM 1024
#define NN 4096
#define TCAND 4
#define FULLMASK 0xffffffffu

typedef unsigned int       u32;
typedef unsigned long long u64;

// ---------------- device scratch (no allocations allowed) ----------------
__device__ int   g_colhit[NN];
__device__ u32   g_colbits[NN / 32];
__device__ float g_rowmax[MM];
__device__ float g_rowsum[MM];
__device__ u64   g_cand[MM * TCAND];   // per-row top-4: key<<32 | col
__device__ float g_gmax;
__device__ float g_gsum;

// Monotonic float -> uint32 ordering key (nonzero for all real floats).
__device__ __forceinline__ u32 orderKey(float v) {
    u32 b = __float_as_uint(v);
    return (b & 0x80000000u) ? ~b : (b | 0x80000000u);
}

// Packed head: key high, inverted flat index (row<<12|col) low 23 bits.
// u64 max == (max key, then smallest flat index) — exact reference tie-break.
__device__ __forceinline__ u64 packHead(u32 key, u32 rc) {
    return ((u64)key << 23) | (u64)(0x400000u - rc);
}

__device__ __forceinline__ u64 u64max(u64 a, u64 b) { return a > b ? a : b; }

// insert into descending top-3 (x1 >= x2 >= x3)
#define INS3(h) do { u64 _h = (h); \
    if (_h > x2) { if (_h > x1) { x3 = x2; x2 = x1; x1 = _h; } \
                   else         { x3 = x2; x2 = _h; } } \
    else if (_h > x3) x3 = _h; } while (0)

// ---------------- K0: column-hit mask (bytes + bitmask) ------------------
__global__ void k0_colhit(const int* __restrict__ cont, const int* __restrict__ prev) {
    int tid = threadIdx.x;                 // 1024 threads
    #pragma unroll
    for (int k = 0; k < 4; k++) g_colhit[tid + k * 1024] = 0;
    if (tid < NN / 32) g_colbits[tid] = 0;
    __syncthreads();
    if (cont[tid]) {
        int c = prev[tid];
        g_colhit[c] = 1;                                  // benign races
        atomicOr(&g_colbits[c >> 5], 1u << (c & 31));
    }
}

// ---------------- K1: per-row rowmax, sumexp, top-4 masked candidates ----
// Block-per-row; candidate rounds: warp-local top-4 (no barriers) + one
// merge by warp 0 (1 barrier total).
__global__ void __launch_bounds__(256) k1_row(const float* __restrict__ scores,
                                              const int* __restrict__ cont) {
    const int r = blockIdx.x, tid = threadIdx.x, lane = tid & 31, warp = tid >> 5;
    __shared__ float wf[8];
    __shared__ float s_bcast;
    __shared__ u64   wtop[32];             // 8 warps x 4 candidates

    const float4* row = (const float4*)(scores + (size_t)r * NN);
    const bool isCont = (cont[r] != 0);    // uniform per block

    float vals[16];
    int   fidx[4];
    #pragma unroll
    for (int k = 0; k < 4; k++) {
        int f = tid + k * 256; fidx[k] = f;
        float4 v = row[f];
        vals[k * 4 + 0] = v.x; vals[k * 4 + 1] = v.y;
        vals[k * 4 + 2] = v.z; vals[k * 4 + 3] = v.w;
    }

    // ---- raw row max ----
    float m = vals[0];
    #pragma unroll
    for (int e = 1; e < 16; e++) m = fmaxf(m, vals[e]);
    #pragma unroll
    for (int off = 16; off; off >>= 1) m = fmaxf(m, __shfl_xor_sync(FULLMASK, m, off));
    if (lane == 0) wf[warp] = m;
    __syncthreads();
    if (warp == 0) {
        float t = (lane < 8) ? wf[lane] : -3.4e38f;
        #pragma unroll
        for (int off = 4; off; off >>= 1) t = fmaxf(t, __shfl_xor_sync(FULLMASK, t, off));
        if (lane == 0) { s_bcast = t; g_rowmax[r] = t; }
    }
    __syncthreads();
    float rowmax = s_bcast;

    // ---- row sumexp (stable at rowmax) ----
    float s = 0.f;
    #pragma unroll
    for (int e = 0; e < 16; e++) s += __expf(vals[e] - rowmax);
    #pragma unroll
    for (int off = 16; off; off >>= 1) s += __shfl_xor_sync(FULLMASK, s, off);
    __syncthreads();
    if (lane == 0) wf[warp] = s;
    __syncthreads();
    if (warp == 0) {
        float t = (lane < 8) ? wf[lane] : 0.f;
        #pragma unroll
        for (int off = 4; off; off >>= 1) t += __shfl_xor_sync(FULLMASK, t, off);
        if (lane == 0) g_rowsum[r] = t;
    }

    // ---- continuing rows: empty candidate list, done (uniform branch) ----
    if (isCont) {
        if (tid < TCAND) g_cand[r * TCAND + tid] = 0ull;
        return;
    }

    // ---- pack once: key<<13 | (4096-col); u64 max == exact tie-break ----
    u64 pk[16];
    #pragma unroll
    for (int k = 0; k < 4; k++) {
        int4 h = ((const int4*)g_colhit)[fidx[k]];
        int hv[4] = { h.x, h.y, h.z, h.w };
        #pragma unroll
        for (int j = 0; j < 4; j++) {
            int col = fidx[k] * 4 + j;
            pk[k * 4 + j] = hv[j] ? 0ull
                : (((u64)orderKey(vals[k * 4 + j]) << 13) | (u64)(4096 - col));
        }
    }

    // ---- warp-local top-4 (4 shuffle rounds, no barriers) ----
    #pragma unroll
    for (int round = 0; round < TCAND; round++) {
        u64 b = 0;
        #pragma unroll
        for (int e = 0; e < 16; e++) b = u64max(b, pk[e]);
        #pragma unroll
        for (int off = 16; off; off >>= 1)
            b = u64max(b, __shfl_xor_sync(FULLMASK, b, off));
        if (lane == 0) wtop[warp * 4 + round] = b;
        if (b) {
            #pragma unroll
            for (int e = 0; e < 16; e++) if (pk[e] == b) pk[e] = 0ull;
        }
    }
    __syncthreads();                        // single barrier

    // ---- warp 0 merges 32 candidates (one per lane) into row top-4 ----
    if (warp == 0) {
        u64 mine = wtop[lane];
        #pragma unroll
        for (int round = 0; round < TCAND; round++) {
            u64 b = mine;
            #pragma unroll
            for (int off = 16; off; off >>= 1)
                b = u64max(b, __shfl_xor_sync(FULLMASK, b, off));
            if (lane == 0) {
                u32 key = (u32)(b >> 13);
                u32 col = 4096u - (u32)(b & 0x1FFFu);
                g_cand[r * TCAND + round] = b ? (((u64)key << 32) | col) : 0ull;
            }
            if (b && mine == b) mine = 0ull;
        }
    }
}

// ---------------- K2: global max + global sum (from row stats) -----------
__global__ void __launch_bounds__(1024) k2_global() {
    int tid = threadIdx.x, lane = tid & 31, warp = tid >> 5;
    __shared__ float w[32];
    __shared__ float s_gm;
    float rm = g_rowmax[tid];
    float m = rm;
    #pragma unroll
    for (int off = 16; off; off >>= 1) m = fmaxf(m, __shfl_xor_sync(FULLMASK, m, off));
    if (lane == 0) w[warp] = m;
    __syncthreads();
    if (warp == 0) {
        float t = w[lane];
        #pragma unroll
        for (int off = 16; off; off >>= 1) t = fmaxf(t, __shfl_xor_sync(FULLMASK, t, off));
        if (lane == 0) s_gm = t;
    }
    __syncthreads();
    float gm = s_gm;
    float s = g_rowsum[tid] * __expf(rm - gm);
    #pragma unroll
    for (int off = 16; off; off >>= 1) s += __shfl_xor_sync(FULLMASK, s, off);
    __syncthreads();
    if (lane == 0) w[warp] = s;
    __syncthreads();
    if (warp == 0) {
        float t = w[lane];
        #pragma unroll
        for (int off = 16; off; off >>= 1) t += __shfl_xor_sync(FULLMASK, t, off);
        if (lane == 0) { g_gmax = gm; g_gsum = t; }
    }
}

// ---------------- K45: fused policy write + greedy assignment ------------
// Change vs 80.4us version: dup columns are RESOLVED via u64 claim-max
// (winner commits; only losers feed the cutoff) instead of excluded.
#define OFF_SHEADS 0
#define OFF_SCAND  8192
#define OFF_CLAIM  40960          /* u64 claim-max array: 32KB */
#define OFF_SGT    73728
#define OFF_COLB   76800
#define OFF_HPTR   77312
#define OFF_MISC   78336
#define DSMEM      78848

__global__ void __launch_bounds__(1024, 1) k45_fused(
        const float* __restrict__ scores,
        const int* __restrict__ cont,
        const int* __restrict__ prev,
        float* __restrict__ out) {
    extern __shared__ char dyn[];
    const int tid = threadIdx.x;

    if (blockIdx.x < 512) {
        // ================= policy =================
        const float gm = g_gmax;
        const float inv = 1.0f / g_gsum;
        int i = blockIdx.x * 1024 + tid;
        const float4* p = (const float4*)scores;
        float4* o = (float4*)(out + MM);
        float4 a = p[i];
        float4 b = p[i + 524288];
        float4 ra, rb;
        ra.x = __expf(a.x - gm) * inv; ra.y = __expf(a.y - gm) * inv;
        ra.z = __expf(a.z - gm) * inv; ra.w = __expf(a.w - gm) * inv;
        rb.x = __expf(b.x - gm) * inv; rb.y = __expf(b.y - gm) * inv;
        rb.z = __expf(b.z - gm) * inv; rb.w = __expf(b.w - gm) * inv;
        o[i] = ra;
        o[i + 524288] = rb;
        return;
    }

    // ================= assignment (block 512) =================
    u64* sheads = (u64*)(dyn + OFF_SHEADS);
    u64* scand  = (u64*)(dyn + OFF_SCAND);
    u64* claim  = (u64*)(dyn + OFF_CLAIM);       // per-column claim-max
    u64* sgt    = (u64*)(dyn + OFF_SGT);         // [0..127]=t1 [128..]=t2 [256..]=t3
    u32* colbits = (u32*)(dyn + OFF_COLB);
    unsigned char* hptr = (unsigned char*)(dyn + OFF_HPTR);
    int* misc = (int*)(dyn + OFF_MISC);
    float* out_act = out;

    // -------- prologue: full block builds shared state --------
    #pragma unroll
    for (int k = 0; k < TCAND; k++) {
        int idx = tid + k * 1024;
        scand[idx] = g_cand[idx];
        claim[idx] = 0ull;
    }
    if (tid < NN / 32) colbits[tid] = g_colbits[tid];
    {
        u64 c0 = g_cand[tid * TCAND];
        u32 key = (u32)(c0 >> 32);
        u32 col = (u32)c0 & 0xFFFu;
        sheads[tid] = key ? packHead(key, ((u32)tid << 12) | col) : 0ull;
    }
    hptr[tid] = 1;
    int myCont = cont[tid];
    out_act[tid] = myCont ? (float)prev[tid] : -1.0f;
    int K = __syncthreads_count(myCont == 0);
    if (tid == 0) misc[0] = K;
    __syncthreads();
    if (tid >= 32) return;

    const int lane = tid;
    const int base = lane * 32;
    const int K2 = misc[0];

    // per-group top-3 cache + lane p1,p2,p3
    u64 p1, p2, p3;
    {
        #pragma unroll
        for (int g = 0; g < 4; g++) {
            u64 x1 = 0, x2 = 0, x3 = 0;
            const ulonglong2* gp = (const ulonglong2*)(sheads + base + g * 8);
            #pragma unroll
            for (int q = 0; q < 4; q++) { ulonglong2 hh = gp[q]; INS3(hh.x); INS3(hh.y); }
            sgt[(lane << 2) + g] = x1;
            sgt[128 + (lane << 2) + g] = x2;
            sgt[256 + (lane << 2) + g] = x3;
        }
        u64 x1 = 0, x2 = 0, x3 = 0;
        #pragma unroll
        for (int g = 0; g < 4; g++) {
            INS3(sgt[(lane << 2) + g]);
            INS3(sgt[128 + (lane << 2) + g]);
            INS3(sgt[256 + (lane << 2) + g]);
        }
        p1 = x1; p2 = x2; p3 = x3;
    }

    int assigned = 0;
    int guard = 0;

    while (assigned < K2) {
        if (++guard > 16384) break;                  // safety (never hit)

        // ---- candidates: lane's top-2 heads (distinct rows) ----
        bool l1 = (p1 != 0ull), l2 = (p2 != 0ull);
        u32 rc1 = 0x400000u - (u32)(p1 & 0x7FFFFFu);
        u32 rc2 = 0x400000u - (u32)(p2 & 0x7FFFFFu);
        int r1 = (int)(rc1 >> 12), c1 = (int)(rc1 & 0xFFFu);
        int r2 = (int)(rc2 >> 12), c2 = (int)(rc2 & 0xFFFu);

        // ---- stale at batch start ----
        bool s1 = l1 && ((colbits[c1 >> 5] >> (c1 & 31)) & 1u);
        bool s2 = l2 && ((colbits[c2 >> 5] >> (c2 & 31)) & 1u);

        // ---- dup resolution among live offers: claim-max per column ----
        bool w1 = l1 && !s1, w2 = l2 && !s2;
        if (w1) atomicMax(&claim[c1], p1);
        if (w2) atomicMax(&claim[c2], p2);
        __syncwarp(FULLMASK);
        bool d1 = w1 && (claim[c1] != p1);     // loser of a column contest
        bool d2 = w2 && (claim[c2] != p2);
        __syncwarp(FULLMASK);
        if (w1) claim[c1] = 0ull;              // same-addr same-val: benign
        if (w2) claim[c2] = 0ull;

        // ---- cutoff S = max(hidden bound p3, stale/loser offer values) ----
        u64 contrib = p3;
        if (s1 || d1) contrib = u64max(contrib, p1);
        if (s2 || d2) contrib = u64max(contrib, p2);
        u32 chi = (u32)(contrib >> 32);
        u32 mh = __reduce_max_sync(FULLMASK, chi);
        u32 clo = (chi == mh) ? (u32)contrib : 0u;
        u32 ml = __reduce_max_sync(FULLMASK, clo);
        u64 S = ((u64)mh << 32) | ml;

        // ---- parallel commits (winners only; exact greedy prefix) ----
        bool k1c = w1 && !d1 && (p1 > S);
        bool k2c = w2 && !d2 && (p2 > S);
        if (k1c) { atomicOr(&colbits[c1 >> 5], 1u << (c1 & 31));
                   out_act[r1] = (float)c1; sheads[r1] = 0ull; }
        if (k2c) { atomicOr(&colbits[c2 >> 5], 1u << (c2 & 31));
                   out_act[r2] = (float)c2; sheads[r2] = 0ull; }
        u32 cb = __ballot_sync(FULLMASK, k1c) ;
        u32 cb2 = __ballot_sync(FULLMASK, k2c);
        assigned += __popc(cb) + __popc(cb2);
        __syncwarp(FULLMASK);

        // ---- fallback single-commit when batch was empty ----
        if (!(cb | cb2)) {
            u32 key = (u32)(p1 >> 23);
            u32 mk = __reduce_max_sync(FULLMASK, key);
            if (mk == 0) break;                       // nothing left (uniform)
            u32 cnd = (key == mk) ? (u32)(p1 & 0x7FFFFFu) : 0u;
            u32 sel = __reduce_max_sync(FULLMASK, cnd);
            u32 rcf = 0x400000u - sel;
            int af = (int)(rcf >> 12), tf = (int)(rcf & 0xFFFu);
            u32 w = colbits[tf >> 5];                 // uniform read
            if (!((w >> (tf & 31)) & 1u)) {
                colbits[tf >> 5] = w | (1u << (tf & 31));   // replicated
                out_act[af] = (float)tf;
                sheads[af] = 0ull;
                assigned++;
                if (lane == (af >> 5)) k1c = true;    // af == r1 for owner
            }
            // if stale: pop phase below handles it
        }

        // ---- pop phase: recheck my two offered rows vs updated colbits ----
        bool ch1 = k1c, ch2 = k2c;
        int rsA = -1, rsB = -1;
        if (l1) {
            u64 h = sheads[r1];
            if (h) {
                u32 hc = (0x400000u - (u32)(h & 0x7FFFFFu)) & 0xFFFu;
                if ((colbits[hc >> 5] >> (hc & 31)) & 1u) {
                    int p = hptr[r1]; u64 np = 0ull;
                    if (p < TCAND) {
                        while (p < TCAND) {
                            u64 cd = scand[(r1 << 2) + p]; p++;
                            u32 kk = (u32)(cd >> 32);
                            if (!kk) { p = TCAND; break; }
                            u32 cc = (u32)cd & 0xFFFu;
                            if (!((colbits[cc >> 5] >> (cc & 31)) & 1u)) {
                                np = packHead(kk, ((u32)r1 << 12) | cc); break;
                            }
                        }
                        hptr[r1] = (unsigned char)p;
                    }
                    if (np) sheads[r1] = np; else rsA = r1;
                    ch1 = true;
                }
            }
        }
        if (l2) {
            u64 h = sheads[r2];
            if (h) {
                u32 hc = (0x400000u - (u32)(h & 0x7FFFFFu)) & 0xFFFu;
                if ((colbits[hc >> 5] >> (hc & 31)) & 1u) {
                    int p = hptr[r2]; u64 np = 0ull;
                    if (p < TCAND) {
                        while (p < TCAND) {
                            u64 cd = scand[(r2 << 2) + p]; p++;
                            u32 kk = (u32)(cd >> 32);
                            if (!kk) { p = TCAND; break; }
                            u32 cc = (u32)cd & 0xFFFu;
                            if (!((colbits[cc >> 5] >> (cc & 31)) & 1u)) {
                                np = packHead(kk, ((u32)r2 << 12) | cc); break;
                            }
                        }
                        hptr[r2] = (unsigned char)p;
                    }
                    if (np) sheads[r2] = np; else rsB = r2;
                    ch2 = true;
                }
            }
        }

        // ---- rare: warp-cooperative exact rescans (list exhausted) ----
        for (;;) {
            int my = (rsA >= 0) ? rsA : rsB;
            u32 rb = __ballot_sync(FULLMASK, my >= 0);
            if (!rb) break;
            int ln = __ffs((int)rb) - 1;
            int ra = __shfl_sync(FULLMASK, my, ln);
            const float4* rp = (const float4*)(scores + (size_t)ra * NN);
            u32 bk = 0, bc = 0xFFFu;
            #pragma unroll 4
            for (int q = 0; q < 32; q++) {
                int f = lane + q * 32;
                float4 vv = rp[f];
                int c0i = f * 4;
                float arr[4] = { vv.x, vv.y, vv.z, vv.w };
                #pragma unroll
                for (int j = 0; j < 4; j++) {
                    int cc = c0i + j;
                    if (!((colbits[cc >> 5] >> (cc & 31)) & 1u)) {
                        u32 kk = orderKey(arr[j]);
                        if (kk > bk) { bk = kk; bc = (u32)cc; }
                    }
                }
            }
            u32 mk2 = __reduce_max_sync(FULLMASK, bk);
            u32 pc = (bk == mk2) ? (0x1000u - bc) : 0u;
            u32 ps = __reduce_max_sync(FULLMASK, pc);
            if (lane == ln) {
                sheads[ra] = mk2 ? packHead(mk2, ((u32)ra << 12) | (0x1000u - ps)) : 0ull;
                hptr[ra] = TCAND;
                if (rsA == ra) rsA = -1; else rsB = -1;
            }
        }
        __syncwarp(FULLMASK);

        // ---- refresh changed groups + lane tops ----
        if (ch1 || ch2) {
            int g1 = (r1 >> 3) & 3, g2 = (r2 >> 3) & 3;
            if (ch1) {
                u64 x1 = 0, x2 = 0, x3 = 0;
                const ulonglong2* gp = (const ulonglong2*)(sheads + base + g1 * 8);
                #pragma unroll
                for (int q = 0; q < 4; q++) { ulonglong2 hh = gp[q]; INS3(hh.x); INS3(hh.y); }
                sgt[(lane << 2) + g1] = x1;
                sgt[128 + (lane << 2) + g1] = x2;
                sgt[256 + (lane << 2) + g1] = x3;
            }
            if (ch2 && (!ch1 || g2 != g1)) {
                u64 x1 = 0, x2 = 0, x3 = 0;
                const ulonglong2* gp = (const ulonglong2*)(sheads + base + g2 * 8);
                #pragma unroll
                for (int q = 0; q < 4; q++) { ulonglong2 hh = gp[q]; INS3(hh.x); INS3(hh.y); }
                sgt[(lane << 2) + g2] = x1;
                sgt[128 + (lane << 2) + g2] = x2;
                sgt[256 + (lane << 2) + g2] = x3;
            }
            u64 x1 = 0, x2 = 0, x3 = 0;
            #pragma unroll
            for (int g = 0; g < 4; g++) {
                INS3(sgt[(lane << 2) + g]);
                INS3(sgt[128 + (lane << 2) + g]);
                INS3(sgt[256 + (lane << 2) + g]);
            }
            p1 = x1; p2 = x2; p3 = x3;
        }
    }
}

// ---------------- launch ---------------------------------------------------
extern "C" void kernel_launch(void* const* d_in, const int* in_sizes, int n_in,
                              void* d_out, int out_size) {
    const float* scores = (const float*)d_in[0];
    const int*   cont   = (const int*)d_in[1];
    const int*   prev   = (const int*)d_in[2];
    float* out = (float*)d_out;      // [0..1023] actions, [1024..] policy

    cudaFuncSetAttribute(k45_fused, cudaFuncAttributeMaxDynamicSharedMemorySize, DSMEM);

    k0_colhit<<<1, 1024>>>(cont, prev);
    k1_row<<<MM, 256>>>(scores, cont);
    k2_global<<<1, 1024>>>();
    k45_fused<<<513, 1024, DSMEM>>>(scores, cont, prev, out);
}